// round 14
// baseline (speedup 1.0000x reference)
#include <cuda_runtime.h>
#include <math.h>

#define NB 8
#define NS 2048
#define NE 1024
#define ND 64
#define NSPLIT 4

// ---------------------------------------------------------------------------
// Static device scratch (allocation-free).
// ---------------------------------------------------------------------------
__device__ float g_Q[NB * NS * ND];
__device__ float g_K[NB * NS * ND];
__device__ float g_V[NB * NS * ND];
__device__ int   g_js[NB * NS];
__device__ int   g_Nv[NB];
__device__ float g_Vmean[NB * ND];
__device__ float g_OP[NSPLIT][(size_t)NB * NS * ND];
__device__ float g_mP[NSPLIT][NB * NS];
__device__ float g_lP[NSPLIT][NB * NS];

// ----------------------------------------------------------------------------
// Kernel A: fused QKV projection, split-N for occupancy.
//   grid (256, 2): blockIdx.x = 64-row m-block, blockIdx.y = 96-col n-half.
//   512 CTAs -> ~3.5 CTAs/SM (was 1.73). Thread tile 4x6.
// ----------------------------------------------------------------------------
__global__ __launch_bounds__(256) void qkv_kernel(
    const float* __restrict__ x,
    const float* __restrict__ Wq, const float* __restrict__ bq,
    const float* __restrict__ Wk, const float* __restrict__ bk,
    const float* __restrict__ Wv, const float* __restrict__ bv)
{
    __shared__ float As[16][68];
    __shared__ float Bs[16][100];   // 96 + pad

    const int tid = threadIdx.x;
    const int tx = tid & 15;
    const int ty = tid >> 4;
    const int m0 = blockIdx.x * 64;
    const int n0 = blockIdx.y * 96;

    float acc[4][6];
    #pragma unroll
    for (int i = 0; i < 4; i++)
        #pragma unroll
        for (int j = 0; j < 6; j++) acc[i][j] = 0.f;

    for (int k0 = 0; k0 < NE; k0 += 16) {
        // A tile: 64x16 = 1024 elems, 4/thread, coalesced 64B rows.
        #pragma unroll
        for (int r = 0; r < 4; r++) {
            int idx = tid + r * 256;
            int row = idx >> 4, col = idx & 15;
            As[col][row] = x[(size_t)(m0 + row) * NE + k0 + col];
        }
        // B tile: 96x16 = 1536 elems, 6/thread.
        #pragma unroll
        for (int r = 0; r < 6; r++) {
            int idx = tid + r * 256;
            int n = idx >> 4, kk = idx & 15;
            int ng = n0 + n;
            const float* W = (ng < 64) ? Wq : ((ng < 128) ? Wk : Wv);
            Bs[kk][n] = W[(size_t)(ng & 63) * NE + k0 + kk];
        }
        __syncthreads();

        #pragma unroll
        for (int k = 0; k < 16; k++) {
            float a[4], bb[6];
            #pragma unroll
            for (int i = 0; i < 4; i++) a[i] = As[k][ty * 4 + i];
            #pragma unroll
            for (int j = 0; j < 6; j++) bb[j] = Bs[k][tx * 6 + j];
            #pragma unroll
            for (int i = 0; i < 4; i++)
                #pragma unroll
                for (int j = 0; j < 6; j++)
                    acc[i][j] = fmaf(a[i], bb[j], acc[i][j]);
        }
        __syncthreads();
    }

    #pragma unroll
    for (int i = 0; i < 4; i++) {
        int m = m0 + ty * 4 + i;
        #pragma unroll
        for (int j = 0; j < 6; j++) {
            int n = n0 + tx * 6 + j;
            float bias = (n < 64) ? bq[n] : ((n < 128) ? bk[n - 64] : bv[n - 128]);
            float v = acc[i][j] + bias;
            if (n < 64)       g_Q[(size_t)m * ND + n] = v;
            else if (n < 128) g_K[(size_t)m * ND + (n - 64)] = v;
            else              g_V[(size_t)m * ND + (n - 128)] = v;
        }
    }
}

// ----------------------------------------------------------------------------
// Kernel P: per-batch prep (mask compaction + V column-mean). Unchanged.
// ----------------------------------------------------------------------------
__global__ __launch_bounds__(256) void prep_kernel(const int* __restrict__ mask)
{
    const int b = blockIdx.x;
    const int tid = threadIdx.x;
    __shared__ int ps[257];
    __shared__ float vred[256];

    const int base = tid * 8;
    int loc[8], cnt = 0;
    #pragma unroll
    for (int u = 0; u < 8; u++) {
        loc[u] = mask[b * NS + base + u];
        cnt += (loc[u] != 0);
    }
    ps[tid + 1] = cnt;
    __syncthreads();
    if (tid == 0) {
        ps[0] = 0;
        for (int t = 1; t <= 256; t++) ps[t] += ps[t - 1];
    }
    __syncthreads();

    int pos = ps[tid];
    #pragma unroll
    for (int u = 0; u < 8; u++) {
        if (loc[u] != 0) g_js[b * NS + pos++] = base + u;
    }
    if (tid == 0) g_Nv[b] = ps[256];

    const int d = tid & 63;
    const int seg = tid >> 6;
    float s = 0.f;
    const float* Vb = &g_V[(size_t)b * NS * ND];
    for (int r = seg * 512; r < seg * 512 + 512; r++)
        s += Vb[(size_t)r * ND + d];
    vred[tid] = s;
    __syncthreads();
    if (tid < 64) {
        float t = vred[tid] + vred[tid + 64] + vred[tid + 128] + vred[tid + 192];
        g_Vmean[b * ND + tid] = t * (1.0f / NS);
    }
}

// ----------------------------------------------------------------------------
// Kernel B: split-KV flash attention (NSPLIT=4) with shuffle reductions.
//   The 16 threads sharing a row (same ty, tx=0..15) occupy one 16-lane
//   half-warp; xor-shuffles over masks {1,2,4,8} reduce row max / row sum.
//   m and l live in registers (replicated across the 16 lanes).
// ----------------------------------------------------------------------------
__global__ __launch_bounds__(256) void attn_kernel()
{
    extern __shared__ float fsm[];
    float* Qs   = fsm;                  // 64*68
    float* Ks   = Qs + 64 * 68;         // 64*68 (aliased by Ps)
    float* Vs   = Ks + 64 * 68;         // 64*68
    int*   js_s = (int*)(Vs + 64 * 68); // 64
    float* Ps   = Ks;                   // alias

    const int tid = threadIdx.x;
    const int tx = tid & 15;
    const int ty = tid >> 4;
    const int b  = blockIdx.y;
    const int i0 = blockIdx.x * 64;
    const int sp = blockIdx.z;

    const int Nv = g_Nv[b];
    const int ntiles = (Nv + 63) >> 6;

    // Binary search: first compacted position with index >= i0.
    int lo = 0, hi = Nv;
    while (lo < hi) {
        int mid = (lo + hi) >> 1;
        if (g_js[b * NS + mid] < i0) lo = mid + 1; else hi = mid;
    }
    const int jt0 = lo >> 6;
    const int nav = ntiles - jt0;
    const int nh  = (nav + NSPLIT - 1) / NSPLIT;
    const int t_begin = jt0 + min(sp * nh, nav);
    const int t_end   = jt0 + min((sp + 1) * nh, nav);

    // Per-thread running max / sum for this thread's 4 rows (replicated x16).
    float m_reg[4], l_reg[4];
    #pragma unroll
    for (int i = 0; i < 4; i++) { m_reg[i] = -INFINITY; l_reg[i] = 0.f; }

    // Load Q tile, pre-scaled by 0.125 (exact power-of-two).
    #pragma unroll
    for (int p = 0; p < 4; p++) {
        int r = p * 16 + ty;
        float4 q = *(const float4*)&g_Q[((size_t)b * NS + i0 + r) * ND + tx * 4];
        q.x *= 0.125f; q.y *= 0.125f; q.z *= 0.125f; q.w *= 0.125f;
        *(float4*)&Qs[r * 68 + tx * 4] = q;
    }

    float o[4][4];
    #pragma unroll
    for (int i = 0; i < 4; i++)
        #pragma unroll
        for (int j = 0; j < 4; j++) o[i][j] = 0.f;

    const int gi_base = i0 + ty * 4;

    for (int jt = t_begin; jt < t_end; jt++) {
        const int j0c = jt * 64;
        __syncthreads();  // prev P@V reads done (Ps/Vs free); Qs ready (iter 0)

        if (tid < 64) {
            int c = j0c + tid;
            js_s[tid] = (c < Nv) ? g_js[b * NS + c] : -1;
        }
        __syncthreads();

        #pragma unroll
        for (int p = 0; p < 4; p++) {
            int r = p * 16 + ty;
            int src = js_s[r];
            if (src < 0) src = 0;
            *(float4*)&Ks[r * 68 + tx * 4] =
                *(const float4*)&g_K[((size_t)b * NS + src) * ND + tx * 4];
            *(float4*)&Vs[r * 68 + tx * 4] =
                *(const float4*)&g_V[((size_t)b * NS + src) * ND + tx * 4];
        }
        __syncthreads();

        // ---- S = Q @ K^T ----
        float s[4][4];
        #pragma unroll
        for (int i = 0; i < 4; i++)
            #pragma unroll
            for (int j = 0; j < 4; j++) s[i][j] = 0.f;

        #pragma unroll
        for (int d = 0; d < 64; d += 4) {
            float qa[4][4], ka[4][4];
            #pragma unroll
            for (int i = 0; i < 4; i++)
                *(float4*)&qa[i][0] = *(float4*)&Qs[(ty * 4 + i) * 68 + d];
            #pragma unroll
            for (int j = 0; j < 4; j++)
                *(float4*)&ka[j][0] = *(float4*)&Ks[(tx * 4 + j) * 68 + d];
            #pragma unroll
            for (int i = 0; i < 4; i++)
                #pragma unroll
                for (int j = 0; j < 4; j++)
                    #pragma unroll
                    for (int cc = 0; cc < 4; cc++)
                        s[i][j] = fmaf(qa[i][cc], ka[j][cc], s[i][j]);
        }

        // ---- mask (scale folded into Q) ----
        #pragma unroll
        for (int i = 0; i < 4; i++) {
            int gi = gi_base + i;
            #pragma unroll
            for (int j = 0; j < 4; j++) {
                bool valid = (js_s[tx * 4 + j] >= gi);
                s[i][j] = valid ? s[i][j] : -1e22f;
            }
        }

        // ---- row max via xor-shuffle over the 16-lane row group ----
        float mn[4], alpha[4];
        #pragma unroll
        for (int i = 0; i < 4; i++) {
            float pm = fmaxf(fmaxf(s[i][0], s[i][1]), fmaxf(s[i][2], s[i][3]));
            #pragma unroll
            for (int msk = 1; msk < 16; msk <<= 1)
                pm = fmaxf(pm, __shfl_xor_sync(0xffffffffu, pm, msk));
            mn[i] = fmaxf(m_reg[i], pm);
            alpha[i] = __expf(m_reg[i] - mn[i]);  // -inf -> 0 on first tile
            m_reg[i] = mn[i];
        }

        __syncthreads();  // all Ks reads complete before Ps (alias) is written

        // ---- p = exp(s - m), write P, rescale O, row-sum via shuffle ----
        #pragma unroll
        for (int i = 0; i < 4; i++) {
            int r = ty * 4 + i;
            float psum = 0.f;
            #pragma unroll
            for (int j = 0; j < 4; j++) {
                float p = __expf(s[i][j] - mn[i]);
                Ps[r * 68 + tx * 4 + j] = p;
                psum += p;
            }
            #pragma unroll
            for (int msk = 1; msk < 16; msk <<= 1)
                psum += __shfl_xor_sync(0xffffffffu, psum, msk);
            #pragma unroll
            for (int j = 0; j < 4; j++) o[i][j] *= alpha[i];
            l_reg[i] = l_reg[i] * alpha[i] + psum;
        }
        __syncthreads();  // Ps ready for all threads

        // ---- O += P @ V ----
        #pragma unroll
        for (int cc = 0; cc < 64; cc += 4) {
            float pa[4][4], va[4][4];
            #pragma unroll
            for (int i = 0; i < 4; i++)
                *(float4*)&pa[i][0] = *(float4*)&Ps[(ty * 4 + i) * 68 + cc];
            #pragma unroll
            for (int k2 = 0; k2 < 4; k2++)
                *(float4*)&va[k2][0] = *(float4*)&Vs[(cc + k2) * 68 + tx * 4];
            #pragma unroll
            for (int i = 0; i < 4; i++)
                #pragma unroll
                for (int dd = 0; dd < 4; dd++)
                    #pragma unroll
                    for (int k2 = 0; k2 < 4; k2++)
                        o[i][dd] = fmaf(pa[i][k2], va[k2][dd], o[i][dd]);
        }
    }

    // Emit partials (unnormalized O, m, l). Empty range -> m=-inf, l=0, O=0.
    #pragma unroll
    for (int i = 0; i < 4; i++) {
        int r = ty * 4 + i;
        float4 v;
        v.x = o[i][0]; v.y = o[i][1]; v.z = o[i][2]; v.w = o[i][3];
        *(float4*)&g_OP[sp][((size_t)b * NS + i0 + r) * ND + tx * 4] = v;
        if (tx == 0) {
            g_mP[sp][b * NS + i0 + r] = m_reg[i];
            g_lP[sp][b * NS + i0 + r] = l_reg[i];
        }
    }
}

// ----------------------------------------------------------------------------
// Kernel M: merge the NSPLIT split-KV partials.
//   m=max_s(m_s); O = sum_s O_s e^{m_s-m} / sum_s l_s e^{m_s-m}.
//   Empty split (m=-inf) and all-invalid split (m=-1e22) get weight 0 when a
//   real max exists; fully-dead rows (m<=-1e21) -> Vmean (uniform softmax).
// ----------------------------------------------------------------------------
__global__ __launch_bounds__(256) void merge_kernel(float* __restrict__ out)
{
    const int idx = blockIdx.x * 256 + threadIdx.x;   // one float4 each
    const int row = idx >> 4;                          // 0 .. NB*NS-1
    const int c   = (idx & 15) * 4;
    const int b   = row >> 11;                         // row / NS

    float m = -INFINITY;
    #pragma unroll
    for (int s = 0; s < NSPLIT; s++) m = fmaxf(m, g_mP[s][row]);

    float4 r;
    if (m <= -1e21f) {
        r = *(const float4*)&g_Vmean[b * ND + c];
    } else {
        float l = 0.f;
        float ax = 0.f, ay = 0.f, az = 0.f, aw = 0.f;
        #pragma unroll
        for (int s = 0; s < NSPLIT; s++) {
            const float e = __expf(g_mP[s][row] - m);  // -inf -> 0
            l += g_lP[s][row] * e;
            const float4 p = *(const float4*)&g_OP[s][(size_t)row * ND + c];
            ax += p.x * e; ay += p.y * e; az += p.z * e; aw += p.w * e;
        }
        const float inv = 1.0f / l;
        r.x = ax * inv; r.y = ay * inv; r.z = az * inv; r.w = aw * inv;
    }
    *(float4*)&out[(size_t)row * ND + c] = r;
}

// ----------------------------------------------------------------------------
// Launch: QKV (split-N) -> prep -> split-KV attention (x4) -> merge.
// ----------------------------------------------------------------------------
extern "C" void kernel_launch(void* const* d_in, const int* in_sizes, int n_in,
                              void* d_out, int out_size)
{
    const float* x    = (const float*)d_in[0];
    const int*   mask = (const int*)  d_in[1];
    const float* Wq   = (const float*)d_in[2];
    const float* bq   = (const float*)d_in[3];
    const float* Wk   = (const float*)d_in[4];
    const float* bk   = (const float*)d_in[5];
    const float* Wv   = (const float*)d_in[6];
    const float* bv   = (const float*)d_in[7];
    float* out = (float*)d_out;

    dim3 qgrid(NB * NS / 64, 2);
    qkv_kernel<<<qgrid, 256>>>(x, Wq, bq, Wk, bk, Wv, bv);
    prep_kernel<<<NB, 256>>>(mask);

    const int ATTN_SMEM = (3 * 64 * 68) * 4 + 64 * 4;   // Q/K/V tiles + js
    cudaFuncSetAttribute(attn_kernel,
                         cudaFuncAttributeMaxDynamicSharedMemorySize, ATTN_SMEM);
    dim3 grid(NS / 64, NB, NSPLIT);
    attn_kernel<<<grid, 256, ATTN_SMEM>>>();

    merge_kernel<<<(NB * NS * ND / 4) / 256, 256>>>(out);
}

// round 15
// speedup vs baseline: 1.2063x; 1.2063x over previous
#include <cuda_runtime.h>
#include <math.h>

#define NB 8
#define NS 2048
#define NE 1024
#define ND 64
#define NSPLIT 2

// ---------------------------------------------------------------------------
// Static device scratch (allocation-free).
// ---------------------------------------------------------------------------
__device__ float g_Q[NB * NS * ND];
__device__ float g_K[NB * NS * ND];
__device__ float g_V[NB * NS * ND];
__device__ int   g_js[NB * NS];
__device__ int   g_Nv[NB];
__device__ float g_Vmean[NB * ND];
__device__ float g_OP[NSPLIT][(size_t)NB * NS * ND];
__device__ float g_mP[NSPLIT][NB * NS];
__device__ float g_lP[NSPLIT][NB * NS];
// QKV k-split partial sums: [row 0..16383][n 0..191]
__device__ float g_P0[(size_t)NB * NS * 192];
__device__ float g_P1[(size_t)NB * NS * 192];

// ----------------------------------------------------------------------------
// Kernel A: QKV projection, 8x12 register tile (FMA-bound), k-split x2.
//   BM=64, BN=192, 128 threads (tx 0..15 -> 12 cols, ty 0..7 -> 8 rows).
//   Per k-step crossbar: 128thr*80B = 10KB = 80cyc < FMA 96cyc -> FMA-bound.
//   blockIdx.y selects k-half [0,512) / [512,1024); partials to g_P0/g_P1.
// ----------------------------------------------------------------------------
__global__ __launch_bounds__(128, 4) void qkv_kernel(
    const float* __restrict__ x,
    const float* __restrict__ Wq, const float* __restrict__ Wk,
    const float* __restrict__ Wv)
{
    __shared__ __align__(16) float As[16][68];    // stride 68 = 0 mod 4 -> f4 ok
    __shared__ __align__(16) float Bs[16][196];   // stride 196 = 0 mod 4

    const int tid = threadIdx.x;
    const int tx = tid & 15;        // n block (12 cols)
    const int ty = tid >> 4;        // m block (8 rows), 0..7
    const int m0 = blockIdx.x * 64;
    const int kb = blockIdx.y * 512;

    float acc[8][12];
    #pragma unroll
    for (int i = 0; i < 8; i++)
        #pragma unroll
        for (int j = 0; j < 12; j++) acc[i][j] = 0.f;

    for (int k0 = 0; k0 < 512; k0 += 16) {
        // A tile 64x16: 8 elems/thread. row = ty + u*8, col = tx.
        #pragma unroll
        for (int u = 0; u < 8; u++) {
            int row = ty + u * 8;
            As[tx][row] = x[(size_t)(m0 + row) * NE + kb + k0 + tx];
        }
        // B tile 192x16: 24 elems/thread. n = ty + u*8, kk = tx.
        // u<8 -> Wq, 8..15 -> Wk, 16..23 -> Wv (n-range fixed per u group).
        #pragma unroll
        for (int u = 0; u < 8; u++) {
            int n = ty + u * 8;
            Bs[tx][n] = Wq[(size_t)n * NE + kb + k0 + tx];
        }
        #pragma unroll
        for (int u = 0; u < 8; u++) {
            int n = ty + u * 8;
            Bs[tx][64 + n] = Wk[(size_t)n * NE + kb + k0 + tx];
        }
        #pragma unroll
        for (int u = 0; u < 8; u++) {
            int n = ty + u * 8;
            Bs[tx][128 + n] = Wv[(size_t)n * NE + kb + k0 + tx];
        }
        __syncthreads();

        #pragma unroll
        for (int k = 0; k < 16; k++) {
            float a[8], bb[12];
            *(float4*)&a[0] = *(const float4*)&As[k][ty * 8];
            *(float4*)&a[4] = *(const float4*)&As[k][ty * 8 + 4];
            *(float4*)&bb[0] = *(const float4*)&Bs[k][tx * 12];
            *(float4*)&bb[4] = *(const float4*)&Bs[k][tx * 12 + 4];
            *(float4*)&bb[8] = *(const float4*)&Bs[k][tx * 12 + 8];
            #pragma unroll
            for (int i = 0; i < 8; i++)
                #pragma unroll
                for (int j = 0; j < 12; j++)
                    acc[i][j] = fmaf(a[i], bb[j], acc[i][j]);
        }
        __syncthreads();
    }

    // Emit partials (no bias here; combine kernel adds it once).
    float* P = blockIdx.y ? g_P1 : g_P0;
    #pragma unroll
    for (int i = 0; i < 8; i++) {
        size_t row = (size_t)(m0 + ty * 8 + i);
        #pragma unroll
        for (int j4 = 0; j4 < 3; j4++) {
            float4 v;
            v.x = acc[i][j4 * 4 + 0]; v.y = acc[i][j4 * 4 + 1];
            v.z = acc[i][j4 * 4 + 2]; v.w = acc[i][j4 * 4 + 3];
            *(float4*)&P[row * 192 + tx * 12 + j4 * 4] = v;
        }
    }
}

// ----------------------------------------------------------------------------
// Kernel C: combine k-split partials + bias -> g_Q / g_K / g_V.
// ----------------------------------------------------------------------------
__global__ __launch_bounds__(256) void combine_kernel(
    const float* __restrict__ bq, const float* __restrict__ bk,
    const float* __restrict__ bv)
{
    const int idx = blockIdx.x * 256 + threadIdx.x;   // float4 id, 16384*48
    const int row = idx / 48;
    const int n   = (idx % 48) * 4;                   // 0..188, 4-aligned

    const float4 p0 = *(const float4*)&g_P0[(size_t)row * 192 + n];
    const float4 p1 = *(const float4*)&g_P1[(size_t)row * 192 + n];

    const float* bias;
    float* dst;
    int nn = n;
    if (n < 64)       { bias = bq; dst = g_Q; }
    else if (n < 128) { bias = bk; dst = g_K; nn = n - 64; }
    else              { bias = bv; dst = g_V; nn = n - 128; }

    float4 v;
    v.x = p0.x + p1.x + bias[nn + 0];
    v.y = p0.y + p1.y + bias[nn + 1];
    v.z = p0.z + p1.z + bias[nn + 2];
    v.w = p0.w + p1.w + bias[nn + 3];
    *(float4*)&dst[(size_t)row * ND + nn] = v;
}

// ----------------------------------------------------------------------------
// Kernel P: per-batch prep (mask compaction + V column-mean). R12 verbatim.
// ----------------------------------------------------------------------------
__global__ __launch_bounds__(256) void prep_kernel(const int* __restrict__ mask)
{
    const int b = blockIdx.x;
    const int tid = threadIdx.x;
    __shared__ int ps[257];
    __shared__ float vred[256];

    const int base = tid * 8;
    int loc[8], cnt = 0;
    #pragma unroll
    for (int u = 0; u < 8; u++) {
        loc[u] = mask[b * NS + base + u];
        cnt += (loc[u] != 0);
    }
    ps[tid + 1] = cnt;
    __syncthreads();
    if (tid == 0) {
        ps[0] = 0;
        for (int t = 1; t <= 256; t++) ps[t] += ps[t - 1];
    }
    __syncthreads();

    int pos = ps[tid];
    #pragma unroll
    for (int u = 0; u < 8; u++) {
        if (loc[u] != 0) g_js[b * NS + pos++] = base + u;
    }
    if (tid == 0) g_Nv[b] = ps[256];

    const int d = tid & 63;
    const int seg = tid >> 6;
    float s = 0.f;
    const float* Vb = &g_V[(size_t)b * NS * ND];
    for (int r = seg * 512; r < seg * 512 + 512; r++)
        s += Vb[(size_t)r * ND + d];
    vred[tid] = s;
    __syncthreads();
    if (tid < 64) {
        float t = vred[tid] + vred[tid + 64] + vred[tid + 128] + vred[tid + 192];
        g_Vmean[b * ND + tid] = t * (1.0f / NS);
    }
}

// ----------------------------------------------------------------------------
// Kernel B: split-KV flash attention (NSPLIT=2, smem reductions). R12 verbatim.
// ----------------------------------------------------------------------------
__global__ __launch_bounds__(256) void attn_kernel()
{
    extern __shared__ float fsm[];
    float* Qs   = fsm;                  // 64*68
    float* Ks   = Qs + 64 * 68;         // 64*68 (aliased by Ps)
    float* Vs   = Ks + 64 * 68;         // 64*68
    float* red  = Vs + 64 * 68;         // 64*16
    float* m_st = red + 64 * 16;        // 64
    float* l_st = m_st + 64;            // 64
    float* al_s = l_st + 64;            // 64
    int*   js_s = (int*)(al_s + 64);    // 64
    float* Ps   = Ks;                   // alias

    const int tid = threadIdx.x;
    const int tx = tid & 15;
    const int ty = tid >> 4;
    const int b  = blockIdx.y;
    const int i0 = blockIdx.x * 64;
    const int sp = blockIdx.z;

    const int Nv = g_Nv[b];
    const int ntiles = (Nv + 63) >> 6;

    int lo = 0, hi = Nv;
    while (lo < hi) {
        int mid = (lo + hi) >> 1;
        if (g_js[b * NS + mid] < i0) lo = mid + 1; else hi = mid;
    }
    const int jt0 = lo >> 6;
    const int nav = ntiles - jt0;
    const int nh  = (nav + 1) >> 1;
    const int t_begin = jt0 + sp * nh;
    const int t_end   = sp ? ntiles : (jt0 + nh);

    if (tid < 64) { m_st[tid] = -INFINITY; l_st[tid] = 0.f; }

    #pragma unroll
    for (int p = 0; p < 4; p++) {
        int r = p * 16 + ty;
        float4 q = *(const float4*)&g_Q[((size_t)b * NS + i0 + r) * ND + tx * 4];
        q.x *= 0.125f; q.y *= 0.125f; q.z *= 0.125f; q.w *= 0.125f;
        *(float4*)&Qs[r * 68 + tx * 4] = q;
    }

    float o[4][4];
    #pragma unroll
    for (int i = 0; i < 4; i++)
        #pragma unroll
        for (int j = 0; j < 4; j++) o[i][j] = 0.f;

    const int gi_base = i0 + ty * 4;

    for (int jt = t_begin; jt < t_end; jt++) {
        const int j0c = jt * 64;
        __syncthreads();

        if (tid < 64) {
            int c = j0c + tid;
            js_s[tid] = (c < Nv) ? g_js[b * NS + c] : -1;
        }
        __syncthreads();

        #pragma unroll
        for (int p = 0; p < 4; p++) {
            int r = p * 16 + ty;
            int src = js_s[r];
            if (src < 0) src = 0;
            *(float4*)&Ks[r * 68 + tx * 4] =
                *(const float4*)&g_K[((size_t)b * NS + src) * ND + tx * 4];
            *(float4*)&Vs[r * 68 + tx * 4] =
                *(const float4*)&g_V[((size_t)b * NS + src) * ND + tx * 4];
        }
        __syncthreads();

        float s[4][4];
        #pragma unroll
        for (int i = 0; i < 4; i++)
            #pragma unroll
            for (int j = 0; j < 4; j++) s[i][j] = 0.f;

        #pragma unroll
        for (int d = 0; d < 64; d += 4) {
            float qa[4][4], ka[4][4];
            #pragma unroll
            for (int i = 0; i < 4; i++)
                *(float4*)&qa[i][0] = *(float4*)&Qs[(ty * 4 + i) * 68 + d];
            #pragma unroll
            for (int j = 0; j < 4; j++)
                *(float4*)&ka[j][0] = *(float4*)&Ks[(tx * 4 + j) * 68 + d];
            #pragma unroll
            for (int i = 0; i < 4; i++)
                #pragma unroll
                for (int j = 0; j < 4; j++)
                    #pragma unroll
                    for (int cc = 0; cc < 4; cc++)
                        s[i][j] = fmaf(qa[i][cc], ka[j][cc], s[i][j]);
        }

        #pragma unroll
        for (int i = 0; i < 4; i++) {
            int gi = gi_base + i;
            #pragma unroll
            for (int j = 0; j < 4; j++) {
                bool valid = (js_s[tx * 4 + j] >= gi);
                s[i][j] = valid ? s[i][j] : -1e22f;
            }
        }

        #pragma unroll
        for (int i = 0; i < 4; i++) {
            float pm = fmaxf(fmaxf(s[i][0], s[i][1]), fmaxf(s[i][2], s[i][3]));
            red[(ty * 4 + i) * 16 + tx] = pm;
        }
        __syncthreads();
        if (tid < 64) {
            const float* rr = &red[tid * 16];
            float mx = rr[0];
            #pragma unroll
            for (int t = 1; t < 16; t++) mx = fmaxf(mx, rr[t]);
            float mo = m_st[tid];
            float mn = fmaxf(mo, mx);
            m_st[tid] = mn;
            al_s[tid] = __expf(mo - mn);
        }
        __syncthreads();

        #pragma unroll
        for (int i = 0; i < 4; i++) {
            int r = ty * 4 + i;
            float mn = m_st[r];
            float a  = al_s[r];
            float psum = 0.f;
            #pragma unroll
            for (int j = 0; j < 4; j++) {
                float p = __expf(s[i][j] - mn);
                Ps[r * 68 + tx * 4 + j] = p;
                psum += p;
            }
            #pragma unroll
            for (int j = 0; j < 4; j++) o[i][j] *= a;
            red[r * 16 + tx] = psum;
        }
        __syncthreads();
        if (tid < 64) {
            const float* rr = &red[tid * 16];
            float sum = 0.f;
            #pragma unroll
            for (int t = 0; t < 16; t++) sum += rr[t];
            l_st[tid] = l_st[tid] * al_s[tid] + sum;
        }

        #pragma unroll
        for (int cc = 0; cc < 64; cc += 4) {
            float pa[4][4], va[4][4];
            #pragma unroll
            for (int i = 0; i < 4; i++)
                *(float4*)&pa[i][0] = *(float4*)&Ps[(ty * 4 + i) * 68 + cc];
            #pragma unroll
            for (int k2 = 0; k2 < 4; k2++)
                *(float4*)&va[k2][0] = *(float4*)&Vs[(cc + k2) * 68 + tx * 4];
            #pragma unroll
            for (int i = 0; i < 4; i++)
                #pragma unroll
                for (int dd = 0; dd < 4; dd++)
                    #pragma unroll
                    for (int k2 = 0; k2 < 4; k2++)
                        o[i][dd] = fmaf(pa[i][k2], va[k2][dd], o[i][dd]);
        }
    }

    __syncthreads();

    #pragma unroll
    for (int i = 0; i < 4; i++) {
        int r = ty * 4 + i;
        float4 v;
        v.x = o[i][0]; v.y = o[i][1]; v.z = o[i][2]; v.w = o[i][3];
        *(float4*)&g_OP[sp][((size_t)b * NS + i0 + r) * ND + tx * 4] = v;
    }
    if (tid < 64) {
        g_mP[sp][b * NS + i0 + tid] = m_st[tid];
        g_lP[sp][b * NS + i0 + tid] = l_st[tid];
    }
}

// ----------------------------------------------------------------------------
// Kernel M: merge the two split-KV partials. R12 verbatim.
// ----------------------------------------------------------------------------
__global__ __launch_bounds__(256) void merge_kernel(float* __restrict__ out)
{
    const int idx = blockIdx.x * 256 + threadIdx.x;
    const int row = idx >> 4;
    const int c   = (idx & 15) * 4;
    const int b   = row >> 11;

    const float m0 = g_mP[0][row];
    const float m1 = g_mP[1][row];
    const float m  = fmaxf(m0, m1);

    float4 r;
    if (m <= -1e21f) {
        r = *(const float4*)&g_Vmean[b * ND + c];
    } else {
        const float e0 = __expf(m0 - m);
        const float e1 = __expf(m1 - m);
        const float l  = g_lP[0][row] * e0 + g_lP[1][row] * e1;
        const float inv = 1.0f / l;
        const float4 a  = *(const float4*)&g_OP[0][(size_t)row * ND + c];
        const float4 bb = *(const float4*)&g_OP[1][(size_t)row * ND + c];
        r.x = (a.x * e0 + bb.x * e1) * inv;
        r.y = (a.y * e0 + bb.y * e1) * inv;
        r.z = (a.z * e0 + bb.z * e1) * inv;
        r.w = (a.w * e0 + bb.w * e1) * inv;
    }
    *(float4*)&out[(size_t)row * ND + c] = r;
}

// ----------------------------------------------------------------------------
// Launch: QKV (k-split) -> combine -> prep -> split-KV attention -> merge.
// ----------------------------------------------------------------------------
extern "C" void kernel_launch(void* const* d_in, const int* in_sizes, int n_in,
                              void* d_out, int out_size)
{
    const float* x    = (const float*)d_in[0];
    const int*   mask = (const int*)  d_in[1];
    const float* Wq   = (const float*)d_in[2];
    const float* bq   = (const float*)d_in[3];
    const float* Wk   = (const float*)d_in[4];
    const float* bk   = (const float*)d_in[5];
    const float* Wv   = (const float*)d_in[6];
    const float* bv   = (const float*)d_in[7];
    float* out = (float*)d_out;

    dim3 qgrid(NB * NS / 64, 2);
    qkv_kernel<<<qgrid, 128>>>(x, Wq, Wk, Wv);
    combine_kernel<<<(NB * NS * 192 / 4) / 256, 256>>>(bq, bk, bv);
    prep_kernel<<<NB, 256>>>(mask);

    const int ATTN_SMEM = (3 * 64 * 68 + 64 * 16 + 3 * 64) * 4 + 64 * 4;
    cudaFuncSetAttribute(attn_kernel,
                         cudaFuncAttributeMaxDynamicSharedMemorySize, ATTN_SMEM);
    dim3 grid(NS / 64, NB, NSPLIT);
    attn_kernel<<<grid, 256, ATTN_SMEM>>>();

    merge_kernel<<<(NB * NS * ND / 4) / 256, 256>>>(out);
}